// round 17
// baseline (speedup 1.0000x reference)
#include <cuda_runtime.h>
#include <cuda_fp16.h>
#include <cstdint>

#define Bb 8
#define Nn 2048
#define Dd 128
#define Fin 10
#define ALPHA 0.02f
typedef unsigned long long ull;

// ---------------- device scratch ----------------
__device__ __align__(16) __half g_Whh[Bb * Nn * Dd];   // 4MB fp16 Wh
__device__ float g_e1[Bb * Nn];
__device__ float g_e2[Bb * Nn];
__device__ float g_P[Bb * Nn];
__device__ float g_R[Bb * Nn];
__device__ __align__(16) float4 g_QS[Bb * Nn];         // (e2, Q, S, 0)
__device__ float g_e2max[Bb] = {-3.402823466e38f, -3.402823466e38f, -3.402823466e38f,
                                -3.402823466e38f, -3.402823466e38f, -3.402823466e38f,
                                -3.402823466e38f, -3.402823466e38f};
__device__ float g_pooled[Bb * Dd];
__device__ int g_ctrB[Bb];      // cumulative; mask &15
__device__ int g_ctr2;          // cumulative; mask &255

// ---------------- helpers ----------------
__device__ __forceinline__ float warpSum(float v) {
#pragma unroll
    for (int o = 16; o > 0; o >>= 1) v += __shfl_xor_sync(0xffffffffu, v, o);
    return v;
}
__device__ __forceinline__ float lrelu(float x) { return fmaxf(x, ALPHA * x); }
__device__ __forceinline__ void atomicMaxFloat(float* a, float v) {
    if (v >= 0.f) atomicMax((int*)a, __float_as_int(v));
    else          atomicMin((unsigned int*)a, __float_as_uint(v));
}
__device__ __forceinline__ void ffma2(ull& a, ull b, ull c) {
    asm("fma.rn.f32x2 %0, %1, %2, %0;" : "+l"(a) : "l"(b), "l"(c));
}
__device__ __forceinline__ ull packf2(float v) {
    ull r; asm("mov.b64 %0, {%1, %1};" : "=l"(r) : "f"(v)); return r;
}
__device__ __forceinline__ uint32_t smem_u32(const void* p) {
    uint32_t a;
    asm("{ .reg .u64 t; cvta.to.shared.u64 t, %1; cvt.u32.u64 %0, t; }" : "=r"(a) : "l"(p));
    return a;
}
__device__ __forceinline__ void ldsm4(uint32_t* r, uint32_t a) {
    asm volatile("ldmatrix.sync.aligned.m8n8.x4.shared.b16 {%0,%1,%2,%3}, [%4];"
        : "=r"(r[0]), "=r"(r[1]), "=r"(r[2]), "=r"(r[3]) : "r"(a));
}
__device__ __forceinline__ void ldsm4t(uint32_t* r, uint32_t a) {
    asm volatile("ldmatrix.sync.aligned.m8n8.x4.trans.shared.b16 {%0,%1,%2,%3}, [%4];"
        : "=r"(r[0]), "=r"(r[1]), "=r"(r[2]), "=r"(r[3]) : "r"(a));
}
__device__ __forceinline__ void mma16816(float* d, const uint32_t* a, uint32_t b0, uint32_t b1) {
    asm volatile("mma.sync.aligned.m16n8k16.row.col.f32.f16.f16.f32 "
        "{%0,%1,%2,%3},{%4,%5,%6,%7},{%8,%9},{%0,%1,%2,%3};"
        : "+f"(d[0]), "+f"(d[1]), "+f"(d[2]), "+f"(d[3])
        : "r"(a[0]), "r"(a[1]), "r"(a[2]), "r"(a[3]), "r"(b0), "r"(b1));
}
__device__ __forceinline__ void cpa16(uint32_t dst, const void* src) {
    asm volatile("cp.async.cg.shared.global [%0], [%1], 16;" :: "r"(dst), "l"(src));
}
__device__ __forceinline__ void cpa_commit() { asm volatile("cp.async.commit_group;"); }
#define BARS(id, cnt) asm volatile("bar.sync %0, %1;" :: "r"(id), "r"(cnt) : "memory")
#define BARA(id, cnt) asm volatile("bar.arrive %0, %1;" :: "r"(id), "r"(cnt) : "memory")

// ---------------- K1: fc1+LN+lrelu -> Wg GEMM -> e1/e2 -> Wh fp16 (+fused k1c tail) ---
__global__ __launch_bounds__(512, 1) void k1(
    const float* __restrict__ h, const float* __restrict__ W1, const float* __restrict__ b1,
    const float* __restrict__ Wg, const float* __restrict__ bg,
    const float* __restrict__ a1, const float* __restrict__ a2)
{
    extern __shared__ __align__(16) float sm[];
    float* wgt = sm;                 // [128 k][132]
    float* xsh = sm + 16896;         // [128 n][129]
    float* hsh = sm + 33408;         // [128 n][10]
    float* w1s = sm + 34688;         // [128 d][10]
    float* b1s = sm + 35968;         // [128]
    float* red = sm + 36096;         // [2][4][128]
    __shared__ int slast;

    const int t = threadIdx.x, lane = t & 31, wrp = t >> 5;
    const int n0 = blockIdx.x * 128;
    const int b  = blockIdx.x >> 4;

#pragma unroll
    for (int it = 0; it < 32; ++it) {
        int idx = it * 512 + t;
        wgt[(idx & 127) * 132 + (idx >> 7)] = Wg[idx];
    }
#pragma unroll
    for (int idx = t; idx < 128 * Fin; idx += 512) {
        hsh[idx] = h[n0 * Fin + idx];
        w1s[idx] = W1[idx];
    }
    if (t < 128) b1s[t] = b1[t];
    __syncthreads();

    {
        const int n = t & 127, qq = t >> 7;
        float hv[Fin];
#pragma unroll
        for (int f = 0; f < Fin; ++f) hv[f] = hsh[n * Fin + f];
        float xr[32], s1 = 0.f, s2 = 0.f;
#pragma unroll
        for (int k = 0; k < 32; ++k) {
            const int d = qq * 32 + k;
            float x = b1s[d];
#pragma unroll
            for (int f = 0; f < Fin; ++f) x += hv[f] * w1s[d * Fin + f];
            xr[k] = x; s1 += x; s2 += x * x;
        }
        red[qq * 128 + n] = s1;
        red[512 + qq * 128 + n] = s2;
        __syncthreads();
        float S1 = red[n] + red[128 + n] + red[256 + n] + red[384 + n];
        float S2 = red[512 + n] + red[640 + n] + red[768 + n] + red[896 + n];
        float mean = S1 * (1.f / Dd);
        float var  = S2 * (1.f / Dd) - mean * mean;
        float rstd = rsqrtf(var + 1e-5f);
#pragma unroll
        for (int k = 0; k < 32; ++k)
            xsh[n * 129 + qq * 32 + k] = lrelu((xr[k] - mean) * rstd);
    }
    __syncthreads();

    ull acc[8][2];
#pragma unroll
    for (int n = 0; n < 8; ++n) { acc[n][0] = 0ull; acc[n][1] = 0ull; }
    for (int k = 0; k < 128; ++k) {
        ulonglong2 wv = *(const ulonglong2*)&wgt[k * 132 + lane * 4];
#pragma unroll
        for (int n = 0; n < 8; ++n) {
            ull xx = packf2(xsh[(wrp * 8 + n) * 129 + k]);
            ffma2(acc[n][0], xx, wv.x);
            ffma2(acc[n][1], xx, wv.y);
        }
    }

    const float4 bgv = ((const float4*)bg)[lane];
    const float4 a1v = ((const float4*)a1)[lane];
    const float4 a2v = ((const float4*)a2)[lane];
    float e2mx = -3.402823466e38f;
#pragma unroll
    for (int n = 0; n < 8; ++n) {
        const int node = n0 + wrp * 8 + n;
        float2 lo = *(float2*)&acc[n][0];
        float2 hi = *(float2*)&acc[n][1];
        float v0 = lo.x + bgv.x, v1 = lo.y + bgv.y;
        float v2 = hi.x + bgv.z, v3 = hi.y + bgv.w;

        ((__half2*)g_Whh)[node * 64 + lane * 2]     = __floats2half2_rn(v0, v1);
        ((__half2*)g_Whh)[node * 64 + lane * 2 + 1] = __floats2half2_rn(v2, v3);

        float p1 = warpSum(v0 * a1v.x + v1 * a1v.y + v2 * a1v.z + v3 * a1v.w);
        float p2 = warpSum(v0 * a2v.x + v1 * a2v.y + v2 * a2v.z + v3 * a2v.w);
        if (lane == 0) {
            g_e1[node] = p1;
            g_e2[node] = p2;
            e2mx = fmaxf(e2mx, p2);
        }
    }
    if (lane == 0) atomicMaxFloat(&g_e2max[b], e2mx);

    // ---- fused k1c tail ----
    __threadfence();
    if (t == 0) slast = ((atomicAdd(&g_ctrB[b], 1) & 15) == 15);
    __syncthreads();
    if (slast) {
        __threadfence();
        float em = g_e2max[b];
        if (t < 128) g_pooled[b * 128 + t] = -3.402823466e38f;
#pragma unroll
        for (int k = 0; k < 4; ++k) {
            int idx = (b << 11) + k * 512 + t;
            float e1 = g_e1[idx], e2 = g_e2[idx];
            float m = lrelu(e1 + em);
            g_P[idx] = __expf(e1 + em - m);
            g_R[idx] = __expf(ALPHA * (e1 + em) - m);
            g_QS[idx] = make_float4(e2, __expf(e2 - em), __expf(ALPHA * (e2 - em)), 0.f);
        }
    }
}

// ---------------- K2: warp-specialized attention, 128-j chunks (+fused k3 tail) ------
// 256 blocks x 256 threads; block = (b, 64 i-rows); 16 chunks of 128 j.
// Warps 0-3: MMA (+Wh cp.async). Warps 4-7: score (direct adj LDG.128).
// smem dyn: WhH[2] @ 0/34816 (128r x 272B); w[2] @ 69632/87040 (64r x 272B). 104448 B.
// Barriers: ready=1,2; free=3,4; mma-overwrite=5; mma-visible=7; joint=6.
__global__ __launch_bounds__(256, 2) void k2_attn(const int* __restrict__ adj,
    const float* __restrict__ W2, const float* __restrict__ b2, float* __restrict__ out)
{
    extern __shared__ __align__(16) char smd[];
    __shared__ float e1s[64], Ps[64], Rs[64], lsh[64];
    __shared__ float red1[64][2], red2[64][2], mrs[64][2];
    __shared__ float pm[4][64];
    __shared__ int slast;

    const int t = threadIdx.x, lane = t & 31, wrp = t >> 5;
    const int b  = blockIdx.x >> 5;
    const int i0 = (blockIdx.x & 31) << 6;
    const uint32_t base = smem_u32(smd);

    if (t < 64) {
        int idx = (b << 11) + i0 + t;
        e1s[t] = g_e1[idx];
        Ps[t]  = g_P[idx];
        Rs[t]  = g_R[idx];
    }
    __syncthreads();

    if (wrp < 4) {
        // ================= MMA warps =================
        float acc[2][8][4];
#pragma unroll
        for (int ib = 0; ib < 2; ++ib)
#pragma unroll
            for (int nt = 0; nt < 8; ++nt)
#pragma unroll
                for (int q = 0; q < 4; ++q) acc[ib][nt][q] = 0.f;

        auto stage_wh = [&](int cc, int bf) {
            const char* sH = (const char*)(g_Whh + ((size_t)((b << 11) + cc * 128) << 7));
            uint32_t dH = base + bf * 34816;
#pragma unroll
            for (int q = 0; q < 16; ++q) {
                int task = q * 128 + t;          // 0..2047
                int row = task >> 4, seg = task & 15;
                cpa16(dH + row * 272 + seg * 16, sH + row * 256 + seg * 16);
            }
        };
        const int iw = (wrp & 1) * 32;
        const int dw = (wrp >> 1) * 64;
        const uint32_t lrr  = ((lane >> 3) & 1) * 8 + (lane & 7);
        const uint32_t csel = (lane >> 4) * 16;

        stage_wh(0, 0); cpa_commit();
        for (int c = 0; c < 16; ++c) {
            const int p = c & 1;
            BARS(5, 128);                  // all mma warps done reading buffer p^1 (chunk c-1)
            if (c < 15) { stage_wh(c + 1, p ^ 1); cpa_commit(); }
            if (c < 15) asm volatile("cp.async.wait_group 1;");
            else        asm volatile("cp.async.wait_group 0;");
            BARS(7, 128);                  // Wh(c) staged by all mma threads
            BARS(1 + p, 256);              // w(c) ready
            {
                uint32_t wH  = base + 69632 + p * 17408;
                uint32_t WhH = base + p * 34816;
                const uint32_t aoff0 = (iw + lrr) * 272 + csel;
                const uint32_t aoff1 = (iw + 16 + lrr) * 272 + csel;
                const uint32_t boffB = lrr * 272 + csel + dw * 2;
#pragma unroll
                for (int ks = 0; ks < 8; ++ks) {
                    uint32_t a0[4], a1[4];
                    ldsm4(a0, wH + aoff0 + ks * 32);
                    ldsm4(a1, wH + aoff1 + ks * 32);
#pragma unroll
                    for (int n2 = 0; n2 < 4; ++n2) {
                        uint32_t bh[4];
                        ldsm4t(bh, WhH + boffB + ks * 16 * 272 + n2 * 32);
                        mma16816(acc[0][2 * n2],     a0, bh[0], bh[1]);
                        mma16816(acc[0][2 * n2 + 1], a0, bh[2], bh[3]);
                        mma16816(acc[1][2 * n2],     a1, bh[0], bh[1]);
                        mma16816(acc[1][2 * n2 + 1], a1, bh[2], bh[3]);
                    }
                }
            }
            BARA(3 + p, 256);              // w buffer p free
        }

        // per-row partials over this warp's d-half
        {
            float S1[4] = {0.f, 0.f, 0.f, 0.f}, S2[4] = {0.f, 0.f, 0.f, 0.f};
#pragma unroll
            for (int ib = 0; ib < 2; ++ib)
#pragma unroll
                for (int nt = 0; nt < 8; ++nt) {
                    float a0 = acc[ib][nt][0], a1 = acc[ib][nt][1];
                    float a2 = acc[ib][nt][2], a3 = acc[ib][nt][3];
                    S1[2 * ib]     += a0 + a1;  S2[2 * ib]     += a0 * a0 + a1 * a1;
                    S1[2 * ib + 1] += a2 + a3;  S2[2 * ib + 1] += a2 * a2 + a3 * a3;
                }
#pragma unroll
            for (int s = 0; s < 4; ++s)
#pragma unroll
                for (int o = 1; o <= 2; o <<= 1) {
                    S1[s] += __shfl_xor_sync(0xffffffffu, S1[s], o);
                    S2[s] += __shfl_xor_sync(0xffffffffu, S2[s], o);
                }
            if ((lane & 3) == 0) {
                const int dh = wrp >> 1;
#pragma unroll
                for (int s = 0; s < 4; ++s) {
                    int row = iw + s * 8 + (lane >> 2);
                    red1[row][dh] = S1[s];
                    red2[row][dh] = S2[s];
                }
            }
        }
        BARS(6, 256);                      // join: lsh (score) + red (mma) visible

        if (t < 64) {
            float S1 = red1[t][0] + red1[t][1];
            float S2 = red2[t][0] + red2[t][1];
            float L  = lsh[t];
            float mean = S1 * (1.f / Dd);
            float var  = S2 * (1.f / Dd) - mean * mean;
            mrs[t][0] = mean;
            mrs[t][1] = rsqrtf(var + 1e-5f * L * L);
        }
        BARS(5, 128);

        {
            float mean_[4], rstd_[4];
#pragma unroll
            for (int s = 0; s < 4; ++s) {
                int row = iw + s * 8 + (lane >> 2);
                mean_[s] = mrs[row][0];
                rstd_[s] = mrs[row][1];
            }
#pragma unroll
            for (int nt = 0; nt < 8; ++nt) {
                float m0 = -3.402823466e38f, m1 = m0;
#pragma unroll
                for (int ib = 0; ib < 2; ++ib) {
                    int slo = 2 * ib, shi = 2 * ib + 1;
                    m0 = fmaxf(m0, lrelu((acc[ib][nt][0] - mean_[slo]) * rstd_[slo]));
                    m1 = fmaxf(m1, lrelu((acc[ib][nt][1] - mean_[slo]) * rstd_[slo]));
                    m0 = fmaxf(m0, lrelu((acc[ib][nt][2] - mean_[shi]) * rstd_[shi]));
                    m1 = fmaxf(m1, lrelu((acc[ib][nt][3] - mean_[shi]) * rstd_[shi]));
                }
#pragma unroll
                for (int o = 4; o <= 16; o <<= 1) {
                    m0 = fmaxf(m0, __shfl_xor_sync(0xffffffffu, m0, o));
                    m1 = fmaxf(m1, __shfl_xor_sync(0xffffffffu, m1, o));
                }
                if (lane < 4) {
                    pm[wrp][nt * 8 + (lane & 3) * 2]     = m0;
                    pm[wrp][nt * 8 + (lane & 3) * 2 + 1] = m1;
                }
            }
        }
        BARS(5, 128);
        {
            float mx = (t < 64) ? fmaxf(pm[0][t], pm[1][t])
                                : fmaxf(pm[2][t - 64], pm[3][t - 64]);
            atomicMaxFloat(&g_pooled[(b << 7) + ((wrp >> 1) ? 64 : 0) + (t & 63)], mx);
        }
    } else {
        // ================= score warps =================
        const int sw = wrp - 4;
        float lsum[16];
#pragma unroll
        for (int r = 0; r < 16; ++r) lsum[r] = 0.f;

        for (int c = 0; c < 16; ++c) {
            const int p = c & 1;
            if (c >= 2) BARS(3 + p, 256);   // w buffer p free (mma(c-2) done)
            // direct adj loads: 16 rows x int4 (4 j per lane)
            int4 av[16];
            const int4* ap = (const int4*)(adj
                + (((size_t)((b << 11) + i0 + sw * 16)) << 11) + c * 128) + lane;
#pragma unroll
            for (int r = 0; r < 16; ++r) av[r] = ap[(size_t)r << 9];
            float4 qs[4];
#pragma unroll
            for (int q = 0; q < 4; ++q) qs[q] = g_QS[(b << 11) + c * 128 + 4 * lane + q];

            const uint32_t wOff = 69632 + p * 17408;
#pragma unroll
            for (int r = 0; r < 16; ++r) {
                const int row = sw * 16 + r;
                float e1r = e1s[row], Pr = Ps[row], Rr = Rs[row];
                float w_[4];
#pragma unroll
                for (int q = 0; q < 4; ++q) {
                    float f = (e1r + qs[q].x >= 0.f) ? Pr * qs[q].y : Rr * qs[q].z;
                    int a = (&av[r].x)[q];
                    w_[q] = a ? f : 0.f;
                    lsum[r] += w_[q];
                }
                __half2 h01 = __floats2half2_rn(w_[0], w_[1]);
                __half2 h23 = __floats2half2_rn(w_[2], w_[3]);
                ull pk = (ull)(*(uint32_t*)&h01) | ((ull)(*(uint32_t*)&h23) << 32);
                *(ull*)(smd + wOff + row * 272 + lane * 8) = pk;
            }
            BARA(1 + p, 256);               // w(c) ready
        }
#pragma unroll
        for (int r = 0; r < 16; ++r) {
            float v = warpSum(lsum[r]);
            if (lane == 0) lsh[sw * 16 + r] = v;
        }
        BARS(6, 256);                       // join
    }

    // ---- fused k3 tail ----
    __syncthreads();
    __threadfence();
    if (t == 0) slast = ((atomicAdd(&g_ctr2, 1) & 255) == 255);
    __syncthreads();
    if (slast) {
        __threadfence();
        const int bo = t >> 5, ln = t & 31;
        float p0 = 0.f, p1 = 0.f;
        for (int d = ln; d < Dd; d += 32) {
            float pv = g_pooled[bo * Dd + d];
            p0 += pv * W2[d];
            p1 += pv * W2[Dd + d];
        }
        p0 = warpSum(p0);
        p1 = warpSum(p1);
        if (ln == 0) {
            float o0 = p0 + b2[0], o1 = p1 + b2[1];
            float m = fmaxf(o0, o1);
            float lse = m + logf(expf(o0 - m) + expf(o1 - m));
            out[bo * 2 + 0] = o0 - lse;
            out[bo * 2 + 1] = o1 - lse;
        }
    }
}

// ---------------- launch ----------------
extern "C" void kernel_launch(void* const* d_in, const int* in_sizes, int n_in,
                              void* d_out, int out_size)
{
    const float* h   = (const float*)d_in[0];
    const int*   adj = (const int*)  d_in[1];
    const float* W1  = (const float*)d_in[2];
    const float* b1  = (const float*)d_in[3];
    const float* Wg  = (const float*)d_in[4];
    const float* bg  = (const float*)d_in[5];
    const float* a1  = (const float*)d_in[6];
    const float* a2  = (const float*)d_in[7];
    const float* W2  = (const float*)d_in[8];
    const float* b2  = (const float*)d_in[9];
    float* out = (float*)d_out;

    const int smem_k1 = 148480;
    const int smem_k2 = 104448;
    cudaFuncSetAttribute(k1, cudaFuncAttributeMaxDynamicSharedMemorySize, smem_k1);
    cudaFuncSetAttribute(k2_attn, cudaFuncAttributeMaxDynamicSharedMemorySize, smem_k2);

    k1<<<128, 512, smem_k1>>>(h, W1, b1, Wg, bg, a1, a2);
    k2_attn<<<256, 256, smem_k2>>>(adj, W2, b2, out);
}